// round 16
// baseline (speedup 1.0000x reference)
#include <cuda_runtime.h>
#include <cuda_bf16.h>
#include <cuda_fp16.h>
#include <math.h>
#include <stdint.h>

#define NPTS  32768
#define NEDGE 786432
#define CIN   16
#define CMID  64
#define COUT  64
#define KMAX  64

// ---------------- device scratch ----------------
// W3T k-index REORDERED: k' = m*16 + c
__device__ __half g_W3T[COUT * 1024];
__device__ int g_start[NPTS + 1];

__device__ __forceinline__ float celu_fast(float x) {
    return fmaxf(x, 0.0f) - 1.0f + __expf(fminf(x, 0.0f));
}
__device__ __forceinline__ uint32_t smem_u32(const void* p) {
    uint32_t a;
    asm("{ .reg .u64 t; cvta.to.shared.u64 t, %1; cvt.u32.u64 %0, t; }" : "=r"(a) : "l"(p));
    return a;
}
__device__ __forceinline__ void cp16(uint32_t dst, const void* src) {
    asm volatile("cp.async.cg.shared.global [%0], [%1], 16;" :: "r"(dst), "l"(src) : "memory");
}
#define CP_COMMIT() asm volatile("cp.async.commit_group;" ::: "memory")
#define CP_WAIT(n)  asm volatile("cp.async.wait_group %0;" :: "n"(n) : "memory")

#define LDMATRIX_X4(r0, r1, r2, r3, addr) \
    asm volatile("ldmatrix.sync.aligned.m8n8.x4.shared.b16 {%0,%1,%2,%3}, [%4];" \
                 : "=r"(r0), "=r"(r1), "=r"(r2), "=r"(r3) : "r"(addr))
#define LDMATRIX_X4_T(r0, r1, r2, r3, addr) \
    asm volatile("ldmatrix.sync.aligned.m8n8.x4.trans.shared.b16 {%0,%1,%2,%3}, [%4];" \
                 : "=r"(r0), "=r"(r1), "=r"(r2), "=r"(r3) : "r"(addr))

#define MMA_FP16(C, A, B0, B1) \
    asm volatile("mma.sync.aligned.m16n8k16.row.col.f32.f16.f16.f32 " \
        "{%0,%1,%2,%3}, {%4,%5,%6,%7}, {%8,%9}, {%0,%1,%2,%3};" \
        : "+f"((C)[0]), "+f"((C)[1]), "+f"((C)[2]), "+f"((C)[3]) \
        : "r"((A)[0]), "r"((A)[1]), "r"((A)[2]), "r"((A)[3]), "r"(B0), "r"(B1))

__device__ __forceinline__ uint32_t pack_half2(float a, float b) {
    __half2 h = __floats2half2_rn(a, b);
    return *(uint32_t*)&h;
}

// ---------------------------------------------------------------------------
// Kernel A: fused aux — offsets + W3 fp16 with k-reorder
// ---------------------------------------------------------------------------
#define NB_OFF ((NEDGE + 255) / 256)
#define NB_W3  ((1024 * 64) / 256)

__global__ void aux_kernel(const int* __restrict__ oi, const float* __restrict__ W3) {
    if (blockIdx.x < NB_OFF) {
        int e = blockIdx.x * 256 + threadIdx.x;
        if (e >= NEDGE) return;
        int v = oi[e];
        if (e == 0) {
            for (int n = 0; n <= v; n++) g_start[n] = 0;
        } else {
            int p = oi[e - 1];
            for (int n = p + 1; n <= v; n++) g_start[n] = e;
        }
        if (e == NEDGE - 1) {
            for (int n = v + 1; n <= NPTS; n++) g_start[n] = NEDGE;
        }
    } else {
        int t = (blockIdx.x - NB_OFF) * 256 + threadIdx.x;
        int k = t >> 6, n = t & 63;
        int c = k >> 6, m = k & 63;
        int kp = m * 16 + c;
        g_W3T[n * 1024 + kp] = __float2half_rn(W3[t]);
    }
}

// ---------------------------------------------------------------------------
// Kernel C: FUSED kernel. 256 thr / 8 warps / 16 points (2 per warp).
// Phase 1: register-chained edge GEMMs per point -> P (fp16) into s_P.
// Phase 2: out[16x64] = s_P[16x1024] @ W3 (streamed via cp.async), + b3.
// ---------------------------------------------------------------------------
#define PHP 48       // s_h / s_x row pitch
#define WHP 48       // s_w2t pitch
#define PPITCH 2064  // s_P row pitch bytes (1032 halfs) — conflict-free ldmatrix
#define BPITCH 80    // B stage row pitch

// dynamic smem layout
#define OFF_SW1   0
#define OFF_W2T   192
#define OFF_SH    3264                   // 8 * 3072
#define OFF_SX    (OFF_SH + 8 * 3072)    // 27840
#define OFF_SP    (OFF_SX + 8 * 3072)    // 52416, 16 * 2064 = 33024
#define OFF_SB    (OFF_SP + 16 * PPITCH) // 85440, 4 stages * 5120
#define SMEM_TOTAL (OFF_SB + 4 * 5120)   // 105920

__global__ __launch_bounds__(256, 2) void fused_kernel(
    const float* __restrict__ x_in,
    const float* __restrict__ pos_in,
    const float* __restrict__ pos_out,
    const int*   __restrict__ in_index,
    const float* __restrict__ W1,
    const float* __restrict__ W2,
    const float* __restrict__ b3,
    float* __restrict__ out)
{
    extern __shared__ char dsm[];
    float* sW1 = (float*)(dsm + OFF_SW1);
    const uint32_t sbase = smem_u32(dsm);

    const int tid  = threadIdx.x;
    const int warp = tid >> 5;
    const int lane = tid & 31;

    // ---- metadata for this warp's 2 points (early, before CTA sync) ----
    int startA[2], cntA[2], myidx[2][2];
#pragma unroll
    for (int p = 0; p < 2; p++) {
        int n = blockIdx.x * 16 + warp * 2 + p;
        startA[p] = __ldg(g_start + n);
        cntA[p]   = __ldg(g_start + n + 1) - startA[p];
        int nl = cntA[p] < KMAX ? cntA[p] : KMAX;
#pragma unroll
        for (int it = 0; it < 2; it++) {
            int e = lane + 32 * it;
            myidx[p][it] = (e < nl) ? __ldg(in_index + startA[p] + e) : -1;
        }
    }

    // ---- CTA-shared weight staging ----
    if (tid < 48) sW1[tid] = W1[tid];
    for (int i = tid; i < 1024; i += 256) {
        int c = i >> 6, m = i & 63;
        *(__half*)(dsm + OFF_W2T + m * WHP + c * 2) = __float2half_rn(W2[i]);
    }
    __syncthreads();

    // hoist W2^T A-fragments
    uint32_t aW2[4][4];
    {
        uint32_t rowOff = (uint32_t)(lane & 15);
        uint32_t colB   = ((lane >> 4) & 1) * 16;
        uint32_t b0 = sbase + OFF_W2T;
#pragma unroll
        for (int mt = 0; mt < 4; mt++) {
            uint32_t a = b0 + (mt * 16 + rowOff) * WHP + colB;
            LDMATRIX_X4(aW2[mt][0], aW2[mt][1], aW2[mt][2], aW2[mt][3], a);
        }
    }

    const uint32_t shB = sbase + OFF_SH + warp * 3072;
    const uint32_t sxB = sbase + OFF_SX + warp * 3072;
    const uint32_t spB = sbase + OFF_SP;

    const uint32_t nRow = (uint32_t)((lane & 7) + ((lane & 16) ? 8 : 0));
    const uint32_t nCol = (lane & 8) ? 16u : 0u;
    const uint32_t tRow = (uint32_t)((lane & 7) + (((lane >> 3) & 1) << 3));
    const uint32_t tCol = ((lane >> 4) & 1) * 16;
    const int g = lane >> 2;
    const int q = lane & 3;

    // ================= PHASE 1: two points per warp =================
#pragma unroll
    for (int p = 0; p < 2; p++) {
        const int n = blockIdx.x * 16 + warp * 2 + p;
        const int cnt = cntA[p];
        const int nl = cnt < KMAX ? cnt : KMAX;
        const int tiles = (nl + 15) >> 4;
        const int epad = tiles * 16;
        const float inv = (cnt > 0) ? (1.0f / (float)cnt) : 0.0f;

        const float po0 = __ldg(pos_out + 3 * n + 0);
        const float po1 = __ldg(pos_out + 3 * n + 1);
        const float po2 = __ldg(pos_out + 3 * n + 2);

        // prologue
#pragma unroll
        for (int it = 0; it < 2; it++) {
            const int e = lane + 32 * it;
            if (e >= epad) break;
            float h[16], x[16];
            const int idx = myidx[p][it];
            if (idx >= 0) {
                float d0 = __ldg(pos_in + 3 * idx + 0) - po0;
                float d1 = __ldg(pos_in + 3 * idx + 1) - po1;
                float d2 = __ldg(pos_in + 3 * idx + 2) - po2;
                const float4* xr = (const float4*)(x_in + (size_t)idx * CIN);
                float4 v0 = __ldg(xr), v1 = __ldg(xr + 1), v2 = __ldg(xr + 2), v3 = __ldg(xr + 3);
#pragma unroll
                for (int c = 0; c < 16; c++) {
                    float a = fmaf(d0, sW1[c], fmaf(d1, sW1[16 + c], d2 * sW1[32 + c]));
                    h[c] = celu_fast(a);
                }
                x[0] = v0.x;  x[1] = v0.y;  x[2] = v0.z;  x[3] = v0.w;
                x[4] = v1.x;  x[5] = v1.y;  x[6] = v1.z;  x[7] = v1.w;
                x[8] = v2.x;  x[9] = v2.y;  x[10] = v2.z; x[11] = v2.w;
                x[12] = v3.x; x[13] = v3.y; x[14] = v3.z; x[15] = v3.w;
            } else {
#pragma unroll
                for (int c = 0; c < 16; c++) { h[c] = 0.0f; x[c] = 0.0f; }
            }
            uint32_t hp[8], xp[8];
#pragma unroll
            for (int j = 0; j < 8; j++) {
                hp[j] = pack_half2(h[2 * j], h[2 * j + 1]);
                xp[j] = pack_half2(x[2 * j], x[2 * j + 1]);
            }
            *(uint4*)(dsm + OFF_SH + warp * 3072 + (uint32_t)e * PHP)      = make_uint4(hp[0], hp[1], hp[2], hp[3]);
            *(uint4*)(dsm + OFF_SH + warp * 3072 + (uint32_t)e * PHP + 16) = make_uint4(hp[4], hp[5], hp[6], hp[7]);
            *(uint4*)(dsm + OFF_SX + warp * 3072 + (uint32_t)e * PHP)      = make_uint4(xp[0], xp[1], xp[2], xp[3]);
            *(uint4*)(dsm + OFF_SX + warp * 3072 + (uint32_t)e * PHP + 16) = make_uint4(xp[4], xp[5], xp[6], xp[7]);
        }
        __syncwarp();

        float P[32];
#pragma unroll
        for (int i = 0; i < 32; i++) P[i] = 0.0f;

        for (int t = 0; t < tiles; t++) {
            uint32_t bH[4], bX[4];
            LDMATRIX_X4(bH[0], bH[1], bH[2], bH[3], shB + (t * 16 + nRow) * PHP + nCol);
            LDMATRIX_X4_T(bX[0], bX[1], bX[2], bX[3], sxB + (t * 16 + tRow) * PHP + tCol);
#pragma unroll
            for (int mt = 0; mt < 4; mt++) {
                float C1a[4] = {0.f, 0.f, 0.f, 0.f};
                float C1b[4] = {0.f, 0.f, 0.f, 0.f};
                MMA_FP16(C1a, aW2[mt], bH[0], bH[1]);
                MMA_FP16(C1b, aW2[mt], bH[2], bH[3]);
                uint32_t aM[4];
                aM[0] = pack_half2(celu_fast(C1a[0]), celu_fast(C1a[1]));
                aM[1] = pack_half2(celu_fast(C1a[2]), celu_fast(C1a[3]));
                aM[2] = pack_half2(celu_fast(C1b[0]), celu_fast(C1b[1]));
                aM[3] = pack_half2(celu_fast(C1b[2]), celu_fast(C1b[3]));
                MMA_FP16(P + mt * 8,     aM, bX[0], bX[1]);
                MMA_FP16(P + mt * 8 + 4, aM, bX[2], bX[3]);
            }
        }
        __syncwarp();   // protect s_h/s_x reuse by next point

        // store P*inv (fp16) to s_P row (warp*2+p), k' = m*16 + c
        char* prow = dsm + OFF_SP + (warp * 2 + p) * PPITCH;
#pragma unroll
        for (int mt = 0; mt < 4; mt++) {
#pragma unroll
            for (int ch = 0; ch < 2; ch++) {
#pragma unroll
                for (int r2 = 0; r2 < 2; r2++) {
                    float v0 = P[mt * 8 + ch * 4 + 2 * r2]     * inv;
                    float v1 = P[mt * 8 + ch * 4 + 2 * r2 + 1] * inv;
                    int m = mt * 16 + g + 8 * r2;
                    int c = ch * 8 + 2 * q;
                    *(uint32_t*)(prow + (m * 16 + c) * 2) = pack_half2(v0, v1);
                }
            }
        }
    }

    // ================= PHASE 2: out[16x64] = s_P @ W3 + b3 =================
    const char* B_g = (const char*)g_W3T;
    const uint32_t sB = sbase + OFF_SB;

    auto issue_B = [&](int kt, int s) {
        uint32_t base = sB + s * 5120;
        int row = tid >> 2, seg = tid & 3;     // 64 rows x 4 segs
        cp16(base + row * BPITCH + seg * 16,
             B_g + (size_t)row * 2048 + kt * 64 + seg * 16);
    };

    issue_B(0, 0); CP_COMMIT();
    issue_B(1, 1); CP_COMMIT();
    issue_B(2, 2); CP_COMMIT();

    float C[2][4];
#pragma unroll
    for (int nt = 0; nt < 2; nt++)
#pragma unroll
        for (int i = 0; i < 4; i++) C[nt][i] = 0.0f;

    const uint32_t aRowB = (uint32_t)(lane & 15) * PPITCH;
    const uint32_t aColB = ((lane >> 4) & 1) * 16;
    const uint32_t bRow  = (lane & 7) + ((lane & 16) ? 8 : 0);
    const uint32_t bColB = (lane & 8) ? 16 : 0;
    const int wN = (warp & 3) * 16;   // n-quarter for warps 0-3

    for (int kt = 0; kt < 32; kt++) {
        CP_WAIT(2);
        __syncthreads();
        if (kt + 3 < 32) issue_B(kt + 3, (kt + 3) & 3);
        CP_COMMIT();

        if (warp < 4) {
            const uint32_t bbase = sB + (kt & 3) * 5120;
#pragma unroll
            for (int ks = 0; ks < 2; ks++) {
                uint32_t a[4];
                LDMATRIX_X4(a[0], a[1], a[2], a[3],
                            spB + aRowB + kt * 64 + ks * 32 + aColB);
                uint32_t b0, b1, b2, b3r;
                LDMATRIX_X4(b0, b1, b2, b3r,
                            bbase + (wN + bRow) * BPITCH + ks * 32 + bColB);
                MMA_FP16(C[0], a, b0, b1);
                MMA_FP16(C[1], a, b2, b3r);
            }
        }
    }

    if (warp < 4) {
        const int q2 = (lane & 3) * 2;
#pragma unroll
        for (int nt = 0; nt < 2; nt++) {
            const int col = wN + nt * 8 + q2;
            float2 bb = *(const float2*)(b3 + col);
            const int row0 = blockIdx.x * 16 + g;
            float2 v0, v1;
            v0.x = C[nt][0] + bb.x;
            v0.y = C[nt][1] + bb.y;
            v1.x = C[nt][2] + bb.x;
            v1.y = C[nt][3] + bb.y;
            *(float2*)(out + (size_t)row0 * COUT + col) = v0;
            *(float2*)(out + (size_t)(row0 + 8) * COUT + col) = v1;
        }
    }
}

// ---------------------------------------------------------------------------
extern "C" void kernel_launch(void* const* d_in, const int* in_sizes, int n_in,
                              void* d_out, int out_size) {
    const float* x_in      = (const float*)d_in[0];
    const float* pos_in    = (const float*)d_in[1];
    const float* pos_out   = (const float*)d_in[2];
    const int*   in_index  = (const int*)d_in[3];
    const int*   out_index = (const int*)d_in[4];
    const float* W1        = (const float*)d_in[5];
    const float* W2        = (const float*)d_in[6];
    const float* W3        = (const float*)d_in[7];
    const float* b3        = (const float*)d_in[8];
    float* out = (float*)d_out;

    cudaFuncSetAttribute(fused_kernel, cudaFuncAttributeMaxDynamicSharedMemorySize, SMEM_TOTAL);

    aux_kernel<<<NB_OFF + NB_W3, 256>>>(out_index, W3);
    fused_kernel<<<NPTS / 16, 256, SMEM_TOTAL>>>(x_in, pos_in, pos_out, in_index,
                                                 W1, W2, b3, out);
}

// round 17
// speedup vs baseline: 1.1578x; 1.1578x over previous
#include <cuda_runtime.h>
#include <cuda_bf16.h>
#include <cuda_fp16.h>
#include <math.h>
#include <stdint.h>

#define NPTS  32768
#define NEDGE 786432
#define CIN   16
#define CMID  64
#define COUT  64
#define KMAX  64

// ---------------- device scratch ----------------
// k-index of P and W3T is REORDERED: k' = m*16 + c
__device__ __half g_P_h[(size_t)NPTS * 1024];
__device__ __half g_W3T[COUT * 1024];
__device__ int g_start[NPTS + 1];

__device__ __forceinline__ float celu_fast(float x) {
    return fmaxf(x, 0.0f) - 1.0f + __expf(fminf(x, 0.0f));
}
__device__ __forceinline__ uint32_t smem_u32(const void* p) {
    uint32_t a;
    asm("{ .reg .u64 t; cvta.to.shared.u64 t, %1; cvt.u32.u64 %0, t; }" : "=r"(a) : "l"(p));
    return a;
}
__device__ __forceinline__ void cp16(uint32_t dst, const void* src) {
    asm volatile("cp.async.cg.shared.global [%0], [%1], 16;" :: "r"(dst), "l"(src) : "memory");
}
#define CP_COMMIT() asm volatile("cp.async.commit_group;" ::: "memory")
#define CP_WAIT(n)  asm volatile("cp.async.wait_group %0;" :: "n"(n) : "memory")

#define LDMATRIX_X4(r0, r1, r2, r3, addr) \
    asm volatile("ldmatrix.sync.aligned.m8n8.x4.shared.b16 {%0,%1,%2,%3}, [%4];" \
                 : "=r"(r0), "=r"(r1), "=r"(r2), "=r"(r3) : "r"(addr))
#define LDMATRIX_X4_T(r0, r1, r2, r3, addr) \
    asm volatile("ldmatrix.sync.aligned.m8n8.x4.trans.shared.b16 {%0,%1,%2,%3}, [%4];" \
                 : "=r"(r0), "=r"(r1), "=r"(r2), "=r"(r3) : "r"(addr))

#define MMA_FP16(C, A, B0, B1) \
    asm volatile("mma.sync.aligned.m16n8k16.row.col.f32.f16.f16.f32 " \
        "{%0,%1,%2,%3}, {%4,%5,%6,%7}, {%8,%9}, {%0,%1,%2,%3};" \
        : "+f"((C)[0]), "+f"((C)[1]), "+f"((C)[2]), "+f"((C)[3]) \
        : "r"((A)[0]), "r"((A)[1]), "r"((A)[2]), "r"((A)[3]), "r"(B0), "r"(B1))

__device__ __forceinline__ uint32_t pack_half2(float a, float b) {
    __half2 h = __floats2half2_rn(a, b);
    return *(uint32_t*)&h;
}

// ---------------------------------------------------------------------------
// Kernel A: fused aux — offsets + W3 fp16 with k-reorder (k' = m*16 + c)
// ---------------------------------------------------------------------------
#define NB_OFF ((NEDGE + 255) / 256)
#define NB_W3  ((1024 * 64) / 256)

__global__ void aux_kernel(const int* __restrict__ oi, const float* __restrict__ W3) {
    if (blockIdx.x < NB_OFF) {
        int e = blockIdx.x * 256 + threadIdx.x;
        if (e >= NEDGE) return;
        int v = oi[e];
        if (e == 0) {
            for (int n = 0; n <= v; n++) g_start[n] = 0;
        } else {
            int p = oi[e - 1];
            for (int n = p + 1; n <= v; n++) g_start[n] = e;
        }
        if (e == NEDGE - 1) {
            for (int n = v + 1; n <= NPTS; n++) g_start[n] = NEDGE;
        }
    } else {
        int t = (blockIdx.x - NB_OFF) * 256 + threadIdx.x;
        int k = t >> 6, n = t & 63;
        int c = k >> 6, m = k & 63;
        int kp = m * 16 + c;
        g_W3T[n * 1024 + kp] = __float2half_rn(W3[t]);
    }
}

// ---------------------------------------------------------------------------
// Kernel C: edge kernel — register-chained GEMMs (R14 proven config).
// ---------------------------------------------------------------------------
#define PHP 48
#define WHP 48

__global__ __launch_bounds__(128) void edge_tc_kernel(
    const float* __restrict__ x_in,
    const float* __restrict__ pos_in,
    const float* __restrict__ pos_out,
    const int*   __restrict__ in_index,
    const float* __restrict__ W1,
    const float* __restrict__ W2)
{
    __shared__ __align__(16) float sW1[48];
    __shared__ __align__(16) char s_w2t[64 * WHP];
    __shared__ __align__(16) char s_h [4][64 * PHP];
    __shared__ __align__(16) char s_x [4][64 * PHP];

    const int tid  = threadIdx.x;
    const int warp = tid >> 5;
    const int lane = tid & 31;

    const int n = blockIdx.x * 4 + warp;
    const int start = __ldg(g_start + n);
    const int cnt   = __ldg(g_start + n + 1) - start;
    const int nl    = cnt < KMAX ? cnt : KMAX;
    const int tiles = (nl + 15) >> 4;
    const int epad  = tiles * 16;
    const float inv = (cnt > 0) ? (1.0f / (float)cnt) : 0.0f;

    const float po0 = __ldg(pos_out + 3 * n + 0);
    const float po1 = __ldg(pos_out + 3 * n + 1);
    const float po2 = __ldg(pos_out + 3 * n + 2);

    int myidx[2];
#pragma unroll
    for (int it = 0; it < 2; it++) {
        int e = lane + 32 * it;
        myidx[it] = (e < nl) ? __ldg(in_index + start + e) : -1;
    }

    if (tid < 48) sW1[tid] = W1[tid];
    for (int i = tid; i < 1024; i += 128) {
        int c = i >> 6, m = i & 63;
        *(__half*)&s_w2t[m * WHP + c * 2] = __float2half_rn(W2[i]);
    }
    __syncthreads();

    uint32_t aW2[4][4];
    {
        uint32_t rowOff = (uint32_t)(lane & 15);
        uint32_t colB   = ((lane >> 4) & 1) * 16;
        uint32_t b0 = smem_u32(s_w2t);
#pragma unroll
        for (int mt = 0; mt < 4; mt++) {
            uint32_t a = (mt * 16 + rowOff) * WHP + colB;
            LDMATRIX_X4(aW2[mt][0], aW2[mt][1], aW2[mt][2], aW2[mt][3], b0 + a);
        }
    }

    float P[32];
#pragma unroll
    for (int i = 0; i < 32; i++) P[i] = 0.0f;

    const uint32_t shB = smem_u32(s_h[warp]);
    const uint32_t sxB = smem_u32(s_x[warp]);

#pragma unroll
    for (int it = 0; it < 2; it++) {
        const int e = lane + 32 * it;
        if (e >= epad) break;
        float h[16], x[16];
        const int idx = myidx[it];
        if (idx >= 0) {
            float d0 = __ldg(pos_in + 3 * idx + 0) - po0;
            float d1 = __ldg(pos_in + 3 * idx + 1) - po1;
            float d2 = __ldg(pos_in + 3 * idx + 2) - po2;
            const float4* xr = (const float4*)(x_in + (size_t)idx * CIN);
            float4 v0 = __ldg(xr), v1 = __ldg(xr + 1), v2 = __ldg(xr + 2), v3 = __ldg(xr + 3);
#pragma unroll
            for (int c = 0; c < 16; c++) {
                float a = fmaf(d0, sW1[c], fmaf(d1, sW1[16 + c], d2 * sW1[32 + c]));
                h[c] = celu_fast(a);
            }
            x[0] = v0.x;  x[1] = v0.y;  x[2] = v0.z;  x[3] = v0.w;
            x[4] = v1.x;  x[5] = v1.y;  x[6] = v1.z;  x[7] = v1.w;
            x[8] = v2.x;  x[9] = v2.y;  x[10] = v2.z; x[11] = v2.w;
            x[12] = v3.x; x[13] = v3.y; x[14] = v3.z; x[15] = v3.w;
        } else {
#pragma unroll
            for (int c = 0; c < 16; c++) { h[c] = 0.0f; x[c] = 0.0f; }
        }
        uint32_t hp[8], xp[8];
#pragma unroll
        for (int j = 0; j < 8; j++) {
            hp[j] = pack_half2(h[2 * j], h[2 * j + 1]);
            xp[j] = pack_half2(x[2 * j], x[2 * j + 1]);
        }
        *(uint4*)(s_h[warp] + (uint32_t)e * PHP)      = make_uint4(hp[0], hp[1], hp[2], hp[3]);
        *(uint4*)(s_h[warp] + (uint32_t)e * PHP + 16) = make_uint4(hp[4], hp[5], hp[6], hp[7]);
        *(uint4*)(s_x[warp] + (uint32_t)e * PHP)      = make_uint4(xp[0], xp[1], xp[2], xp[3]);
        *(uint4*)(s_x[warp] + (uint32_t)e * PHP + 16) = make_uint4(xp[4], xp[5], xp[6], xp[7]);
    }
    __syncwarp();

    const uint32_t nRow = (uint32_t)((lane & 7) + ((lane & 16) ? 8 : 0));
    const uint32_t nCol = (lane & 8) ? 16u : 0u;
    const uint32_t tRow = (uint32_t)((lane & 7) + (((lane >> 3) & 1) << 3));
    const uint32_t tCol = ((lane >> 4) & 1) * 16;
    const int g = lane >> 2;
    const int q = lane & 3;

    for (int t = 0; t < tiles; t++) {
        uint32_t bH[4], bX[4];
        LDMATRIX_X4(bH[0], bH[1], bH[2], bH[3], shB + (t * 16 + nRow) * PHP + nCol);
        LDMATRIX_X4_T(bX[0], bX[1], bX[2], bX[3], sxB + (t * 16 + tRow) * PHP + tCol);

#pragma unroll
        for (int mt = 0; mt < 4; mt++) {
            float C1a[4] = {0.f, 0.f, 0.f, 0.f};
            float C1b[4] = {0.f, 0.f, 0.f, 0.f};
            MMA_FP16(C1a, aW2[mt], bH[0], bH[1]);
            MMA_FP16(C1b, aW2[mt], bH[2], bH[3]);
            uint32_t aM[4];
            aM[0] = pack_half2(celu_fast(C1a[0]), celu_fast(C1a[1]));
            aM[1] = pack_half2(celu_fast(C1a[2]), celu_fast(C1a[3]));
            aM[2] = pack_half2(celu_fast(C1b[0]), celu_fast(C1b[1]));
            aM[3] = pack_half2(celu_fast(C1b[2]), celu_fast(C1b[3]));
            MMA_FP16(P + mt * 8,     aM, bX[0], bX[1]);
            MMA_FP16(P + mt * 8 + 4, aM, bX[2], bX[3]);
        }
    }

    __half* dp = g_P_h + (size_t)n * 1024;
#pragma unroll
    for (int mt = 0; mt < 4; mt++) {
#pragma unroll
        for (int ch = 0; ch < 2; ch++) {
#pragma unroll
            for (int r2 = 0; r2 < 2; r2++) {
                float v0 = P[mt * 8 + ch * 4 + 2 * r2]     * inv;
                float v1 = P[mt * 8 + ch * 4 + 2 * r2 + 1] * inv;
                int m = mt * 16 + g + 8 * r2;
                int c = ch * 8 + 2 * q;
                *(uint32_t*)(dp + m * 16 + c) = pack_half2(v0, v1);
            }
        }
    }
}

// ---------------------------------------------------------------------------
// Kernel D: out = P @ W3 + b3. M=128/CTA, 256 thr, single-fp16 W3, 6-stage
// cp.async with wait-lag 4 (covers DRAM latency; 2 CTAs/SM at 92KB smem).
// ---------------------------------------------------------------------------
#define PITCH_B 80
#define OFF_A   0
#define OFF_B   10240
#define STAGE_BYTES 15360
#define NSTAGE 6
#define GEMM_SMEM (NSTAGE * STAGE_BYTES)

__global__ __launch_bounds__(256) void gemm_mma(
    const float* __restrict__ b3,
    float* __restrict__ out)
{
    extern __shared__ char dsm[];
    const uint32_t sbase = smem_u32(dsm);

    const int tid  = threadIdx.x;
    const int warp = tid >> 5;
    const int lane = tid & 31;
    const int ctaM = blockIdx.x * 128;

    const char* A_g = (const char*)(g_P_h + (size_t)ctaM * 1024);
    const char* B_g = (const char*)g_W3T;

    auto issue_loads = [&](int kt, int s) {
        uint32_t base = sbase + s * STAGE_BYTES;
        const int kb = kt * 64;
#pragma unroll
        for (int i = 0; i < 2; i++) {
            int idx = tid + i * 256;              // A: 128 rows x 4 segs
            int row = idx >> 2, seg = idx & 3;
            uint32_t d = base + OFF_A + row * PITCH_B + seg * 16;
            cp16(d, A_g + (size_t)row * 2048 + kb + seg * 16);
        }
        {
            int row = tid >> 2, seg = tid & 3;    // B: 64 rows x 4 segs
            uint32_t d = base + OFF_B + row * PITCH_B + seg * 16;
            cp16(d, B_g + (size_t)row * 2048 + kb + seg * 16);
        }
    };

    float C[8][4];
#pragma unroll
    for (int nt = 0; nt < 8; nt++)
#pragma unroll
        for (int i = 0; i < 4; i++) C[nt][i] = 0.0f;

    const uint32_t aRow  = warp * 16 + (lane & 15);
    const uint32_t aColB = ((lane >> 4) & 1) * 16;
    const uint32_t bRow  = (lane & 7) + ((lane & 16) ? 8 : 0);
    const uint32_t bColB = (lane & 8) ? 16 : 0;

    // prologue: fill 5 stages
#pragma unroll
    for (int s = 0; s < 5; s++) {
        issue_loads(s, s);
        CP_COMMIT();
    }

    int scons = 0;   // stage being consumed
    int sprod = 5;   // next stage to fill
    for (int kt = 0; kt < 32; kt++) {
        CP_WAIT(4);
        __syncthreads();
        if (kt + 5 < 32) {
            issue_loads(kt + 5, sprod);
            if (++sprod == NSTAGE) sprod = 0;
        }
        CP_COMMIT();

        const uint32_t base = sbase + scons * STAGE_BYTES;
#pragma unroll
        for (int ks = 0; ks < 2; ks++) {
            const uint32_t kOffB = ks * 32;
            uint32_t a[4];
            LDMATRIX_X4(a[0], a[1], a[2], a[3],
                        base + OFF_A + aRow * PITCH_B + kOffB + aColB);
#pragma unroll
            for (int p = 0; p < 4; p++) {
                uint32_t b0, b1, b2, b3r;
                uint32_t ba = base + OFF_B + (p * 16 + bRow) * PITCH_B + kOffB + bColB;
                LDMATRIX_X4(b0, b1, b2, b3r, ba);
                MMA_FP16(C[2 * p],     a, b0, b1);
                MMA_FP16(C[2 * p + 1], a, b2, b3r);
            }
        }
        if (++scons == NSTAGE) scons = 0;
    }

    const int g  = lane >> 2;
    const int q2 = (lane & 3) * 2;
    const int rowBase = ctaM + warp * 16;
#pragma unroll
    for (int nt = 0; nt < 8; nt++) {
        const int col = nt * 8 + q2;
        float2 bb = *(const float2*)(b3 + col);
        float2 v0, v1;
        v0.x = C[nt][0] + bb.x;
        v0.y = C[nt][1] + bb.y;
        v1.x = C[nt][2] + bb.x;
        v1.y = C[nt][3] + bb.y;
        *(float2*)(out + (size_t)(rowBase + g) * COUT + col) = v0;
        *(float2*)(out + (size_t)(rowBase + g + 8) * COUT + col) = v1;
    }
}

// ---------------------------------------------------------------------------
extern "C" void kernel_launch(void* const* d_in, const int* in_sizes, int n_in,
                              void* d_out, int out_size) {
    const float* x_in      = (const float*)d_in[0];
    const float* pos_in    = (const float*)d_in[1];
    const float* pos_out   = (const float*)d_in[2];
    const int*   in_index  = (const int*)d_in[3];
    const int*   out_index = (const int*)d_in[4];
    const float* W1        = (const float*)d_in[5];
    const float* W2        = (const float*)d_in[6];
    const float* W3        = (const float*)d_in[7];
    const float* b3        = (const float*)d_in[8];
    float* out = (float*)d_out;

    cudaFuncSetAttribute(gemm_mma, cudaFuncAttributeMaxDynamicSharedMemorySize, GEMM_SMEM);

    aux_kernel<<<NB_OFF + NB_W3, 256>>>(out_index, W3);
    edge_tc_kernel<<<NPTS / 4, 128>>>(x_in, pos_in, pos_out, in_index, W1, W2);
    gemm_mma<<<NPTS / 128, 256, GEMM_SMEM>>>(b3, out);
}